// round 1
// baseline (speedup 1.0000x reference)
#include <cuda_runtime.h>
#include <cuda_fp16.h>

// ---------------------------------------------------------------------------
// SemanticActor fused kernel (fp16 mma.sync, fp32 accumulate)
//
// Pipeline per CTA (64 batch rows):
//   for 6 object pairs: gather inp(64x80) -> GEMM1(K=80) -> relu ->
//                       GEMM2(K=256) -> relu -> accumulate (registers)
//   rho GEMM(K=256) -> relu -> heads (256->4 x2) -> clip -> out
// Weights staged in SMEM as fp16, pre-transposed/padded by a prologue kernel.
// ---------------------------------------------------------------------------

__constant__ int cFIRST[20]  = {0,1,2,3,4,5,6,7,8,9,10,11,12,13,15,16,17,20,21,25};
__constant__ int cSECOND[20] = {0,1,2,3,4,5,6,7,8,9,14,18,19,22,23,24,26,27,28,29};
__constant__ int cPI[6] = {0,0,1,1,2,2};
__constant__ int cPJ[6] = {1,2,0,2,0,1};
__constant__ int cPF[6] = {1,1,0,1,0,0};

// Padded, transposed fp16 weights: Wt[n][k], row stride padded (+8 halves)
// to make mma fragment loads bank-conflict-free.
__device__ __align__(16) __half gW1t[256 * 88];    // phi_w1 (80x256)  -> [n][k] ld=88
__device__ __align__(16) __half gW2t[256 * 264];   // phi_w2 (256x256) -> [n][k] ld=264
__device__ __align__(16) __half gRHOt[256 * 264];  // rho_w1 (256x256) -> [n][k] ld=264

__global__ void convert_weights_kernel(const float* __restrict__ w1,
                                       const float* __restrict__ w2,
                                       const float* __restrict__ rho) {
    int idx = blockIdx.x * blockDim.x + threadIdx.x;
    if (idx >= 256 * 256) return;
    int k = idx >> 8;
    int n = idx & 255;
    gW2t[n * 264 + k]  = __float2half_rn(w2[idx]);
    gRHOt[n * 264 + k] = __float2half_rn(rho[idx]);
    if (k < 80) gW1t[n * 88 + k] = __float2half_rn(w1[idx]);  // w1[k*256+n] == w1[idx]
}

__device__ __forceinline__ void mma16816(float c[4],
                                         unsigned a0, unsigned a1, unsigned a2, unsigned a3,
                                         unsigned b0, unsigned b1) {
    asm volatile(
        "mma.sync.aligned.m16n8k16.row.col.f32.f16.f16.f32 "
        "{%0,%1,%2,%3},{%4,%5,%6,%7},{%8,%9},{%0,%1,%2,%3};"
        : "+f"(c[0]), "+f"(c[1]), "+f"(c[2]), "+f"(c[3])
        : "r"(a0), "r"(a1), "r"(a2), "r"(a3), "r"(b0), "r"(b1));
}

// 16x128 warp tile GEMM: acc += A[row0:row0+16, 0:16*ksteps] * B^T
// A: row-major [m][k] fp16, stride lda (halves). B: Wt[n][k] fp16, stride ldb.
__device__ __forceinline__ void gemm_tile(const __half* __restrict__ As, int lda,
                                          const __half* __restrict__ Bs, int ldb,
                                          int ksteps, float acc[16][4],
                                          int row0, int col0, int r, int q) {
    for (int ks = 0; ks < ksteps; ++ks) {
        const int k0 = ks * 16;
        const __half* ap = As + (row0 + r) * lda + k0 + q * 2;
        unsigned a0 = *(const unsigned*)(ap);
        unsigned a1 = *(const unsigned*)(ap + 8 * lda);
        unsigned a2 = *(const unsigned*)(ap + 8);
        unsigned a3 = *(const unsigned*)(ap + 8 * lda + 8);
        const __half* bp = Bs + (col0 + r) * ldb + k0 + q * 2;
#pragma unroll
        for (int nt = 0; nt < 16; ++nt) {
            unsigned b0 = *(const unsigned*)(bp + nt * 8 * ldb);
            unsigned b1 = *(const unsigned*)(bp + nt * 8 * ldb + 8);
            mma16816(acc[nt], a0, a1, a2, a3, b0, b1);
        }
    }
}

// SMEM layout (bytes):
//   [0,      11264)  inp tile 64x88 fp16         (later reused: head weights fp32 8KB)
//   [11264,  45056)  h tile   64x264 fp16
//   [45056,  90112)  W1t      256x88 fp16
//   [90112, 225280)  W2t/RHOt 256x264 fp16
//   [225280,228352)  biases b1,b2,b3 fp32 (3x256)
#define SMEM_BYTES 228352

__global__ void __launch_bounds__(256, 1)
actor_kernel(const float* __restrict__ obs, const float* __restrict__ ag,
             const float* __restrict__ g,
             const float* __restrict__ b1g, const float* __restrict__ b2g,
             const float* __restrict__ b3g,
             const float* __restrict__ mean_w, const float* __restrict__ mean_b,
             const float* __restrict__ logstd_w, const float* __restrict__ logstd_b,
             float* __restrict__ out, int B) {
    extern __shared__ char smem[];
    __half* inp_s  = (__half*)(smem);
    __half* h_s    = (__half*)(smem + 11264);
    __half* w1_s   = (__half*)(smem + 45056);
    __half* w2_s   = (__half*)(smem + 90112);
    float*  bias_s = (float*)(smem + 225280);
    float*  hw_s   = (float*)(smem);  // head weights, reuses inp region at the end

    const int tid  = threadIdx.x;
    const int lane = tid & 31;
    const int warp = tid >> 5;
    const int wm = warp >> 1;            // 0..3  (row group)
    const int wn = warp & 1;             // 0..1  (col group)
    const int r  = lane >> 2;            // groupID
    const int q  = lane & 3;             // threadID_in_group
    const int row0 = wm * 16;
    const int col0 = wn * 128;
    const int rowbase = blockIdx.x * 64;

    // --- stage biases + weights into SMEM ---
    bias_s[tid]       = b1g[tid & 255];   // tid<256 exactly
    bias_s[256 + tid] = b2g[tid & 255];
    bias_s[512 + tid] = b3g[tid & 255];
    {
        const uint4* s1 = (const uint4*)gW1t;
        uint4* d1 = (uint4*)w1_s;
        for (int i = tid; i < 256 * 88 * 2 / 16; i += 256) d1[i] = s1[i];
        const uint4* s2 = (const uint4*)gW2t;
        uint4* d2 = (uint4*)w2_s;
        for (int i = tid; i < 256 * 264 * 2 / 16; i += 256) d2[i] = s2[i];
    }

    float agg[16][4];
#pragma unroll
    for (int nt = 0; nt < 16; ++nt) {
        agg[nt][0] = 0.f; agg[nt][1] = 0.f; agg[nt][2] = 0.f; agg[nt][3] = 0.f;
    }
    float acc[16][4];

    __syncthreads();

    // ============================ pair loop ============================
    for (int p = 0; p < 6; ++p) {
        // gather inp tile (64x80) : [sel(ag) | body | sel(g) | obj_i | obj_j]
        {
            const int i_ = cPI[p], j_ = cPJ[p];
            const int* sel = cPF[p] ? cFIRST : cSECOND;
            const int oi = 10 + 15 * i_;
            const int oj = 10 + 15 * j_;
            for (int e = tid; e < 64 * 80; e += 256) {
                int rr = e / 80;
                int c  = e - rr * 80;
                int gr = rowbase + rr;
                float v = 0.f;
                if (gr < B) {
                    if (c < 20)      v = ag[gr * 30 + sel[c]];
                    else if (c < 30) v = obs[gr * 55 + (c - 20)];
                    else if (c < 50) v = g[gr * 30 + sel[c - 30]];
                    else if (c < 65) v = obs[gr * 55 + oi + (c - 50)];
                    else             v = obs[gr * 55 + oj + (c - 65)];
                }
                inp_s[rr * 88 + c] = __float2half_rn(v);
            }
        }
        __syncthreads();  // inp ready (also: nobody still reading previous inp)

        // GEMM1: acc = inp @ W1  (K=80)
#pragma unroll
        for (int nt = 0; nt < 16; ++nt) {
            acc[nt][0] = 0.f; acc[nt][1] = 0.f; acc[nt][2] = 0.f; acc[nt][3] = 0.f;
        }
        gemm_tile(inp_s, 88, w1_s, 88, 5, acc, row0, col0, r, q);
        __syncthreads();  // all warps done GEMM1; h safe to overwrite (prev GEMM2 done too)

        // epilogue1: h = relu(acc + b1) -> fp16 SMEM
#pragma unroll
        for (int nt = 0; nt < 16; ++nt) {
            const int cb = col0 + nt * 8 + q * 2;
            const float bx = bias_s[cb], by = bias_s[cb + 1];
            __half2 v01 = __floats2half2_rn(fmaxf(acc[nt][0] + bx, 0.f),
                                            fmaxf(acc[nt][1] + by, 0.f));
            __half2 v23 = __floats2half2_rn(fmaxf(acc[nt][2] + bx, 0.f),
                                            fmaxf(acc[nt][3] + by, 0.f));
            *(__half2*)&h_s[(row0 + r)     * 264 + cb] = v01;
            *(__half2*)&h_s[(row0 + r + 8) * 264 + cb] = v23;
        }
        __syncthreads();  // h ready

        // GEMM2: acc = h @ W2 (K=256), then agg += relu(acc + b2)
#pragma unroll
        for (int nt = 0; nt < 16; ++nt) {
            acc[nt][0] = 0.f; acc[nt][1] = 0.f; acc[nt][2] = 0.f; acc[nt][3] = 0.f;
        }
        gemm_tile(h_s, 264, w2_s, 264, 16, acc, row0, col0, r, q);
#pragma unroll
        for (int nt = 0; nt < 16; ++nt) {
            const int cb = col0 + nt * 8 + q * 2;
            const float bx = bias_s[256 + cb], by = bias_s[256 + cb + 1];
            agg[nt][0] += fmaxf(acc[nt][0] + bx, 0.f);
            agg[nt][1] += fmaxf(acc[nt][1] + by, 0.f);
            agg[nt][2] += fmaxf(acc[nt][2] + bx, 0.f);
            agg[nt][3] += fmaxf(acc[nt][3] + by, 0.f);
        }
    }

    __syncthreads();  // all GEMM2 reads of h_s / w2_s complete

    // stage rho weights over W2 region; dump agg (fp16) into h_s as GEMM3 A
    {
        const uint4* s2 = (const uint4*)gRHOt;
        uint4* d2 = (uint4*)w2_s;
        for (int i = tid; i < 256 * 264 * 2 / 16; i += 256) d2[i] = s2[i];
    }
#pragma unroll
    for (int nt = 0; nt < 16; ++nt) {
        const int cb = col0 + nt * 8 + q * 2;
        *(__half2*)&h_s[(row0 + r)     * 264 + cb] = __floats2half2_rn(agg[nt][0], agg[nt][1]);
        *(__half2*)&h_s[(row0 + r + 8) * 264 + cb] = __floats2half2_rn(agg[nt][2], agg[nt][3]);
    }
    __syncthreads();

    // GEMM3: acc = agg @ rho (K=256)
#pragma unroll
    for (int nt = 0; nt < 16; ++nt) {
        acc[nt][0] = 0.f; acc[nt][1] = 0.f; acc[nt][2] = 0.f; acc[nt][3] = 0.f;
    }
    gemm_tile(h_s, 264, w2_s, 264, 16, acc, row0, col0, r, q);
    __syncthreads();  // everyone done reading h_s before hr overwrite

    // epilogue3: hr = relu(acc + b3) -> h_s fp16 ; stage head weights
#pragma unroll
    for (int nt = 0; nt < 16; ++nt) {
        const int cb = col0 + nt * 8 + q * 2;
        const float bx = bias_s[512 + cb], by = bias_s[512 + cb + 1];
        __half2 v01 = __floats2half2_rn(fmaxf(acc[nt][0] + bx, 0.f),
                                        fmaxf(acc[nt][1] + by, 0.f));
        __half2 v23 = __floats2half2_rn(fmaxf(acc[nt][2] + bx, 0.f),
                                        fmaxf(acc[nt][3] + by, 0.f));
        *(__half2*)&h_s[(row0 + r)     * 264 + cb] = v01;
        *(__half2*)&h_s[(row0 + r + 8) * 264 + cb] = v23;
    }
    for (int i = tid; i < 1024; i += 256) {
        hw_s[i]        = mean_w[i];
        hw_s[1024 + i] = logstd_w[i];
    }
    __syncthreads();

    // heads: mean / logstd (256 -> 4 each), logstd clipped to [-20, 2]
    for (int idx = tid; idx < 512; idx += 256) {
        const int row = idx >> 3;
        const int o = idx & 7;
        const int head = o >> 2;
        const int j = o & 3;
        const int gr = rowbase + row;
        const __half2* hp = (const __half2*)&h_s[row * 264];
        const float* wp = hw_s + head * 1024 + j;
        float s = 0.f;
#pragma unroll 8
        for (int k2 = 0; k2 < 128; ++k2) {
            float2 hv = __half22float2(hp[k2]);
            s += hv.x * wp[(2 * k2) * 4] + hv.y * wp[(2 * k2 + 1) * 4];
        }
        s += head ? logstd_b[j] : mean_b[j];
        if (head) s = fminf(fmaxf(s, -20.f), 2.f);
        if (gr < B) out[(head ? (size_t)B * 4 : (size_t)0) + (size_t)gr * 4 + j] = s;
    }
}

extern "C" void kernel_launch(void* const* d_in, const int* in_sizes, int n_in,
                              void* d_out, int out_size) {
    const float* obs = (const float*)d_in[0];
    const float* ag  = (const float*)d_in[1];
    const float* g   = (const float*)d_in[2];
    const float* w1  = (const float*)d_in[3];
    const float* b1  = (const float*)d_in[4];
    const float* w2  = (const float*)d_in[5];
    const float* b2  = (const float*)d_in[6];
    const float* rho = (const float*)d_in[7];
    const float* b3  = (const float*)d_in[8];
    const float* mw  = (const float*)d_in[9];
    const float* mb  = (const float*)d_in[10];
    const float* lw  = (const float*)d_in[11];
    const float* lb  = (const float*)d_in[12];
    float* out = (float*)d_out;
    const int B = in_sizes[0] / 55;

    convert_weights_kernel<<<(256 * 256 + 255) / 256, 256>>>(w1, w2, rho);

    cudaFuncSetAttribute(actor_kernel,
                         cudaFuncAttributeMaxDynamicSharedMemorySize, SMEM_BYTES);
    actor_kernel<<<(B + 63) / 64, 256, SMEM_BYTES>>>(obs, ag, g, b1, b2, b3,
                                                     mw, mb, lw, lb, out, B);
}

// round 2
// speedup vs baseline: 1.2366x; 1.2366x over previous
#include <cuda_runtime.h>
#include <cuda_fp16.h>

// ---------------------------------------------------------------------------
// SemanticActor fused kernel v2: fp16 mma.sync + ldmatrix, 512 threads/CTA.
// CTA = 64 batch rows; 16 warps in 4(M) x 4(N) grid, warp tile 16x64.
// ---------------------------------------------------------------------------

__constant__ int cFIRST[20]  = {0,1,2,3,4,5,6,7,8,9,10,11,12,13,15,16,17,20,21,25};
__constant__ int cSECOND[20] = {0,1,2,3,4,5,6,7,8,9,14,18,19,22,23,24,26,27,28,29};
__constant__ int cPI[6] = {0,0,1,1,2,2};
__constant__ int cPJ[6] = {1,2,0,2,0,1};
__constant__ int cPF[6] = {1,1,0,1,0,0};

// Padded, transposed fp16 weights: Wt[n][k], row stride padded (+8 halves)
__device__ __align__(16) __half gW1t[256 * 88];    // phi_w1 (80x256)  ld=88
__device__ __align__(16) __half gW2t[256 * 264];   // phi_w2 (256x256) ld=264
__device__ __align__(16) __half gRHOt[256 * 264];  // rho_w1 (256x256) ld=264

__global__ void convert_weights_kernel(const float* __restrict__ w1,
                                       const float* __restrict__ w2,
                                       const float* __restrict__ rho) {
    int idx = blockIdx.x * blockDim.x + threadIdx.x;
    if (idx >= 256 * 256) return;
    int k = idx >> 8;
    int n = idx & 255;
    gW2t[n * 264 + k]  = __float2half_rn(w2[idx]);
    gRHOt[n * 264 + k] = __float2half_rn(rho[idx]);
    if (k < 80) gW1t[n * 88 + k] = __float2half_rn(w1[idx]);
}

__device__ __forceinline__ void mma16816(float c[4],
                                         unsigned a0, unsigned a1, unsigned a2, unsigned a3,
                                         unsigned b0, unsigned b1) {
    asm volatile(
        "mma.sync.aligned.m16n8k16.row.col.f32.f16.f16.f32 "
        "{%0,%1,%2,%3},{%4,%5,%6,%7},{%8,%9},{%0,%1,%2,%3};"
        : "+f"(c[0]), "+f"(c[1]), "+f"(c[2]), "+f"(c[3])
        : "r"(a0), "r"(a1), "r"(a2), "r"(a3), "r"(b0), "r"(b1));
}

__device__ __forceinline__ void ldsm4(unsigned& r0, unsigned& r1, unsigned& r2, unsigned& r3,
                                      unsigned addr) {
    asm volatile("ldmatrix.sync.aligned.m8n8.x4.shared.b16 {%0,%1,%2,%3}, [%4];"
                 : "=r"(r0), "=r"(r1), "=r"(r2), "=r"(r3) : "r"(addr));
}

// Warp-tile GEMM 16x64: acc += A[row0:+16, :16*KSTEPS] * Wt^T[col0:+64, :]
// aAddr: this lane's ldmatrix address into A at k=0 (byte, shared space)
// bAddr[j]: this lane's ldmatrix address into B n-block j (j*16 cols) at k=0
template <int KSTEPS>
__device__ __forceinline__ void gemm_tile(unsigned aAddr, const unsigned bAddr[4],
                                          float acc[8][4]) {
#pragma unroll
    for (int ks = 0; ks < KSTEPS; ++ks) {
        unsigned a0, a1, a2, a3;
        ldsm4(a0, a1, a2, a3, aAddr + ks * 32);
#pragma unroll
        for (int j = 0; j < 4; ++j) {
            unsigned b0, b1, b2, b3;
            ldsm4(b0, b1, b2, b3, bAddr[j] + ks * 32);
            mma16816(acc[2 * j],     a0, a1, a2, a3, b0, b1);
            mma16816(acc[2 * j + 1], a0, a1, a2, a3, b2, b3);
        }
    }
}

// SMEM layout (bytes):
//   [0,      11264)  inp tile 64x88 fp16   (reused for head weights fp32 8KB)
//   [11264,  45056)  h tile   64x264 fp16
//   [45056,  90112)  W1t      256x88 fp16
//   [90112, 225280)  W2t/RHOt 256x264 fp16
//   [225280,228352)  biases b1,b2,b3 fp32 (3x256)
#define SMEM_BYTES 228352
#define NTHREADS 512

__global__ void __launch_bounds__(NTHREADS, 1)
actor_kernel(const float* __restrict__ obs, const float* __restrict__ ag,
             const float* __restrict__ g,
             const float* __restrict__ b1g, const float* __restrict__ b2g,
             const float* __restrict__ b3g,
             const float* __restrict__ mean_w, const float* __restrict__ mean_b,
             const float* __restrict__ logstd_w, const float* __restrict__ logstd_b,
             float* __restrict__ out, int B) {
    extern __shared__ char smem[];
    __half* inp_s  = (__half*)(smem);
    __half* h_s    = (__half*)(smem + 11264);
    __half* w1_s   = (__half*)(smem + 45056);
    __half* w2_s   = (__half*)(smem + 90112);
    float*  bias_s = (float*)(smem + 225280);
    float*  hw_s   = (float*)(smem);  // head weights (reuses inp region at end)

    const int tid  = threadIdx.x;
    const int lane = tid & 31;
    const int warp = tid >> 5;
    const int wm = warp >> 2;            // 0..3 (row group, 16 rows)
    const int wn = warp & 3;             // 0..3 (col group, 64 cols)
    const int r  = lane >> 2;
    const int q  = lane & 3;
    const int row0 = wm * 16;
    const int col0 = wn * 64;
    const int rowbase = blockIdx.x * 64;

    // ldmatrix per-lane offsets
    const int aRow = (lane & 7) + ((lane >> 3) & 1) * 8;   // row within 16
    const int aK   = (lane >> 4) * 8;                      // k offset (halves)
    const int bN   = (lane >> 4) * 8 + (lane & 7);         // n within 16
    const int bK   = ((lane >> 3) & 1) * 8;                // k offset (halves)

    const unsigned inp_sh = (unsigned)__cvta_generic_to_shared(inp_s);
    const unsigned h_sh   = (unsigned)__cvta_generic_to_shared(h_s);
    const unsigned w1_sh  = (unsigned)__cvta_generic_to_shared(w1_s);
    const unsigned w2_sh  = (unsigned)__cvta_generic_to_shared(w2_s);

    // A addresses (bytes)
    const unsigned aInp = inp_sh + ((row0 + aRow) * 88  + aK) * 2;
    const unsigned aH   = h_sh   + ((row0 + aRow) * 264 + aK) * 2;
    // B addresses per 16-col block
    unsigned bW1[4], bW2[4];
#pragma unroll
    for (int j = 0; j < 4; ++j) {
        bW1[j] = w1_sh + ((col0 + j * 16 + bN) * 88  + bK) * 2;
        bW2[j] = w2_sh + ((col0 + j * 16 + bN) * 264 + bK) * 2;
    }

    // --- stage biases + weights into SMEM ---
    for (int i = tid; i < 768; i += NTHREADS)
        bias_s[i] = (i < 256) ? b1g[i] : (i < 512 ? b2g[i - 256] : b3g[i - 512]);
    {
        const uint4* s1 = (const uint4*)gW1t;
        uint4* d1 = (uint4*)w1_s;
        for (int i = tid; i < 256 * 88 * 2 / 16; i += NTHREADS) d1[i] = s1[i];
        const uint4* s2 = (const uint4*)gW2t;
        uint4* d2 = (uint4*)w2_s;
        for (int i = tid; i < 256 * 264 * 2 / 16; i += NTHREADS) d2[i] = s2[i];
    }

    float agg[8][4];
#pragma unroll
    for (int nt = 0; nt < 8; ++nt) {
        agg[nt][0] = 0.f; agg[nt][1] = 0.f; agg[nt][2] = 0.f; agg[nt][3] = 0.f;
    }
    float acc[8][4];

    __syncthreads();

    // ============================ pair loop ============================
    for (int p = 0; p < 6; ++p) {
        // gather inp tile (64x80): [sel(ag) | body | sel(g) | obj_i | obj_j]
        {
            const int i_ = cPI[p], j_ = cPJ[p];
            const int* sel = cPF[p] ? cFIRST : cSECOND;
            const int oi = 10 + 15 * i_;
            const int oj = 10 + 15 * j_;
            for (int e = tid; e < 64 * 80; e += NTHREADS) {
                int rr = e / 80;
                int c  = e - rr * 80;
                int gr = rowbase + rr;
                float v = 0.f;
                if (gr < B) {
                    if (c < 20)      v = ag[gr * 30 + sel[c]];
                    else if (c < 30) v = obs[gr * 55 + (c - 20)];
                    else if (c < 50) v = g[gr * 30 + sel[c - 30]];
                    else if (c < 65) v = obs[gr * 55 + oi + (c - 50)];
                    else             v = obs[gr * 55 + oj + (c - 65)];
                }
                inp_s[rr * 88 + c] = __float2half_rn(v);
            }
        }
        __syncthreads();  // inp ready; prior GEMM2 reads of h_s done

        // GEMM1: acc = inp @ W1 (K=80)
#pragma unroll
        for (int nt = 0; nt < 8; ++nt) {
            acc[nt][0] = 0.f; acc[nt][1] = 0.f; acc[nt][2] = 0.f; acc[nt][3] = 0.f;
        }
        gemm_tile<5>(aInp, bW1, acc);
        __syncthreads();  // h_s safe to overwrite

        // epilogue1: h = relu(acc + b1) -> fp16 SMEM
#pragma unroll
        for (int nt = 0; nt < 8; ++nt) {
            const int cb = col0 + nt * 8 + q * 2;
            const float bx = bias_s[cb], by = bias_s[cb + 1];
            __half2 v01 = __floats2half2_rn(fmaxf(acc[nt][0] + bx, 0.f),
                                            fmaxf(acc[nt][1] + by, 0.f));
            __half2 v23 = __floats2half2_rn(fmaxf(acc[nt][2] + bx, 0.f),
                                            fmaxf(acc[nt][3] + by, 0.f));
            *(__half2*)&h_s[(row0 + r)     * 264 + cb] = v01;
            *(__half2*)&h_s[(row0 + r + 8) * 264 + cb] = v23;
        }
        __syncthreads();  // h ready

        // GEMM2: acc = h @ W2 (K=256); agg += relu(acc + b2)
#pragma unroll
        for (int nt = 0; nt < 8; ++nt) {
            acc[nt][0] = 0.f; acc[nt][1] = 0.f; acc[nt][2] = 0.f; acc[nt][3] = 0.f;
        }
        gemm_tile<16>(aH, bW2, acc);
#pragma unroll
        for (int nt = 0; nt < 8; ++nt) {
            const int cb = col0 + nt * 8 + q * 2;
            const float bx = bias_s[256 + cb], by = bias_s[256 + cb + 1];
            agg[nt][0] += fmaxf(acc[nt][0] + bx, 0.f);
            agg[nt][1] += fmaxf(acc[nt][1] + by, 0.f);
            agg[nt][2] += fmaxf(acc[nt][2] + bx, 0.f);
            agg[nt][3] += fmaxf(acc[nt][3] + by, 0.f);
        }
    }

    __syncthreads();  // all GEMM2 reads of h_s / w2_s complete

    // stage rho over W2; dump agg (fp16) into h_s as GEMM3 A operand
    {
        const uint4* s2 = (const uint4*)gRHOt;
        uint4* d2 = (uint4*)w2_s;
        for (int i = tid; i < 256 * 264 * 2 / 16; i += NTHREADS) d2[i] = s2[i];
    }
#pragma unroll
    for (int nt = 0; nt < 8; ++nt) {
        const int cb = col0 + nt * 8 + q * 2;
        *(__half2*)&h_s[(row0 + r)     * 264 + cb] = __floats2half2_rn(agg[nt][0], agg[nt][1]);
        *(__half2*)&h_s[(row0 + r + 8) * 264 + cb] = __floats2half2_rn(agg[nt][2], agg[nt][3]);
    }
    __syncthreads();

    // GEMM3: acc = agg @ rho (K=256)
#pragma unroll
    for (int nt = 0; nt < 8; ++nt) {
        acc[nt][0] = 0.f; acc[nt][1] = 0.f; acc[nt][2] = 0.f; acc[nt][3] = 0.f;
    }
    gemm_tile<16>(aH, bW2, acc);
    __syncthreads();  // all reads of h_s done before hr overwrite

    // epilogue3: hr = relu(acc + b3) -> h_s; stage head weights
#pragma unroll
    for (int nt = 0; nt < 8; ++nt) {
        const int cb = col0 + nt * 8 + q * 2;
        const float bx = bias_s[512 + cb], by = bias_s[512 + cb + 1];
        __half2 v01 = __floats2half2_rn(fmaxf(acc[nt][0] + bx, 0.f),
                                        fmaxf(acc[nt][1] + by, 0.f));
        __half2 v23 = __floats2half2_rn(fmaxf(acc[nt][2] + bx, 0.f),
                                        fmaxf(acc[nt][3] + by, 0.f));
        *(__half2*)&h_s[(row0 + r)     * 264 + cb] = v01;
        *(__half2*)&h_s[(row0 + r + 8) * 264 + cb] = v23;
    }
    for (int i = tid; i < 2048; i += NTHREADS)
        hw_s[i] = (i < 1024) ? mean_w[i] : logstd_w[i - 1024];
    __syncthreads();

    // heads: mean / logstd (256 -> 4 each); logstd clipped to [-20, 2]
    {
        const int idx = tid;  // 512 outputs, one per thread
        const int row = idx >> 3;
        const int o = idx & 7;
        const int head = o >> 2;
        const int j = o & 3;
        const int gr = rowbase + row;
        const __half2* hp = (const __half2*)&h_s[row * 264];
        const float* wp = hw_s + head * 1024 + j;
        float s = 0.f;
#pragma unroll 8
        for (int k2 = 0; k2 < 128; ++k2) {
            float2 hv = __half22float2(hp[k2]);
            s += hv.x * wp[(2 * k2) * 4] + hv.y * wp[(2 * k2 + 1) * 4];
        }
        s += head ? logstd_b[j] : mean_b[j];
        if (head) s = fminf(fmaxf(s, -20.f), 2.f);
        if (gr < B) out[(head ? (size_t)B * 4 : (size_t)0) + (size_t)gr * 4 + j] = s;
    }
}

extern "C" void kernel_launch(void* const* d_in, const int* in_sizes, int n_in,
                              void* d_out, int out_size) {
    const float* obs = (const float*)d_in[0];
    const float* ag  = (const float*)d_in[1];
    const float* g   = (const float*)d_in[2];
    const float* w1  = (const float*)d_in[3];
    const float* b1  = (const float*)d_in[4];
    const float* w2  = (const float*)d_in[5];
    const float* b2  = (const float*)d_in[6];
    const float* rho = (const float*)d_in[7];
    const float* b3  = (const float*)d_in[8];
    const float* mw  = (const float*)d_in[9];
    const float* mb  = (const float*)d_in[10];
    const float* lw  = (const float*)d_in[11];
    const float* lb  = (const float*)d_in[12];
    float* out = (float*)d_out;
    const int B = in_sizes[0] / 55;

    convert_weights_kernel<<<(256 * 256 + 255) / 256, 256>>>(w1, w2, rho);

    cudaFuncSetAttribute(actor_kernel,
                         cudaFuncAttributeMaxDynamicSharedMemorySize, SMEM_BYTES);
    actor_kernel<<<(B + 63) / 64, NTHREADS, SMEM_BYTES>>>(obs, ag, g, b1, b2, b3,
                                                          mw, mb, lw, lb, out, B);
}

// round 5
// speedup vs baseline: 1.2972x; 1.0490x over previous
#include <cuda_runtime.h>
#include <cuda_fp16.h>

// ---------------------------------------------------------------------------
// SemanticActor fused kernel v4: fp16 mma.sync + ldmatrix, 1024 threads/CTA.
// CTA = 64 batch rows; 32 warps in 4(M) x 8(N) grid, warp tile 16x32.
// (tcgen05 unavailable: harness ptxas targets sm_103 without 'a' features.)
// ---------------------------------------------------------------------------

__constant__ int cFIRST[20]  = {0,1,2,3,4,5,6,7,8,9,10,11,12,13,15,16,17,20,21,25};
__constant__ int cSECOND[20] = {0,1,2,3,4,5,6,7,8,9,14,18,19,22,23,24,26,27,28,29};
__constant__ int cPI[6] = {0,0,1,1,2,2};
__constant__ int cPJ[6] = {1,2,0,2,0,1};
__constant__ int cPF[6] = {1,1,0,1,0,0};

// Padded, transposed fp16 weights: Wt[n][k], row stride padded (+8 halves)
__device__ __align__(16) __half gW1t[256 * 88];    // phi_w1 (80x256)  ld=88
__device__ __align__(16) __half gW2t[256 * 264];   // phi_w2 (256x256) ld=264
__device__ __align__(16) __half gRHOt[256 * 264];  // rho_w1 (256x256) ld=264

__global__ void convert_weights_kernel(const float* __restrict__ w1,
                                       const float* __restrict__ w2,
                                       const float* __restrict__ rho) {
    int idx = blockIdx.x * blockDim.x + threadIdx.x;
    if (idx >= 256 * 256) return;
    int k = idx >> 8;
    int n = idx & 255;
    gW2t[n * 264 + k]  = __float2half_rn(w2[idx]);
    gRHOt[n * 264 + k] = __float2half_rn(rho[idx]);
    if (k < 80) gW1t[n * 88 + k] = __float2half_rn(w1[idx]);
}

__device__ __forceinline__ void mma16816(float c[4],
                                         unsigned a0, unsigned a1, unsigned a2, unsigned a3,
                                         unsigned b0, unsigned b1) {
    asm volatile(
        "mma.sync.aligned.m16n8k16.row.col.f32.f16.f16.f32 "
        "{%0,%1,%2,%3},{%4,%5,%6,%7},{%8,%9},{%0,%1,%2,%3};"
        : "+f"(c[0]), "+f"(c[1]), "+f"(c[2]), "+f"(c[3])
        : "r"(a0), "r"(a1), "r"(a2), "r"(a3), "r"(b0), "r"(b1));
}

__device__ __forceinline__ void ldsm4(unsigned& r0, unsigned& r1, unsigned& r2, unsigned& r3,
                                      unsigned addr) {
    asm volatile("ldmatrix.sync.aligned.m8n8.x4.shared.b16 {%0,%1,%2,%3}, [%4];"
                 : "=r"(r0), "=r"(r1), "=r"(r2), "=r"(r3) : "r"(addr));
}

// Warp-tile GEMM 16x32: acc += A[row0:+16, :16*KSTEPS] * Wt^T[col0:+32, :]
template <int KSTEPS>
__device__ __forceinline__ void gemm_tile(unsigned aAddr, const unsigned bAddr[2],
                                          float acc[4][4]) {
#pragma unroll
    for (int ks = 0; ks < KSTEPS; ++ks) {
        unsigned a0, a1, a2, a3;
        ldsm4(a0, a1, a2, a3, aAddr + ks * 32);
#pragma unroll
        for (int j = 0; j < 2; ++j) {
            unsigned b0, b1, b2, b3;
            ldsm4(b0, b1, b2, b3, bAddr[j] + ks * 32);
            mma16816(acc[2 * j],     a0, a1, a2, a3, b0, b1);
            mma16816(acc[2 * j + 1], a0, a1, a2, a3, b2, b3);
        }
    }
}

// SMEM layout (bytes):
//   [0,      11264)  inp tile 64x88 fp16   (reused for head weights fp32 8KB)
//   [11264,  45056)  h tile   64x264 fp16
//   [45056,  90112)  W1t      256x88 fp16
//   [90112, 225280)  W2t/RHOt 256x264 fp16
//   [225280,228352)  biases b1,b2,b3 fp32 (3x256)
#define SMEM_BYTES 228352
#define NTHREADS 1024

__global__ void __launch_bounds__(NTHREADS, 1)
actor_kernel(const float* __restrict__ obs, const float* __restrict__ ag,
             const float* __restrict__ g,
             const float* __restrict__ b1g, const float* __restrict__ b2g,
             const float* __restrict__ b3g,
             const float* __restrict__ mean_w, const float* __restrict__ mean_b,
             const float* __restrict__ logstd_w, const float* __restrict__ logstd_b,
             float* __restrict__ out, int B) {
    extern __shared__ char smem[];
    __half* inp_s  = (__half*)(smem);
    __half* h_s    = (__half*)(smem + 11264);
    __half* w1_s   = (__half*)(smem + 45056);
    __half* w2_s   = (__half*)(smem + 90112);
    float*  bias_s = (float*)(smem + 225280);
    float*  hw_s   = (float*)(smem);  // head weights (reuses inp region at end)

    const int tid  = threadIdx.x;
    const int lane = tid & 31;
    const int warp = tid >> 5;
    const int wm = warp >> 3;            // 0..3 (row group, 16 rows)
    const int wn = warp & 7;             // 0..7 (col group, 32 cols)
    const int r  = lane >> 2;
    const int q  = lane & 3;
    const int row0 = wm * 16;
    const int col0 = wn * 32;
    const int rowbase = blockIdx.x * 64;

    // ldmatrix per-lane offsets
    const int aRow = (lane & 7) + ((lane >> 3) & 1) * 8;   // row within 16
    const int aK   = (lane >> 4) * 8;                      // k offset (halves)
    const int bN   = (lane >> 4) * 8 + (lane & 7);         // n within 16
    const int bK   = ((lane >> 3) & 1) * 8;                // k offset (halves)

    const unsigned inp_sh = (unsigned)__cvta_generic_to_shared(inp_s);
    const unsigned h_sh   = (unsigned)__cvta_generic_to_shared(h_s);
    const unsigned w1_sh  = (unsigned)__cvta_generic_to_shared(w1_s);
    const unsigned w2_sh  = (unsigned)__cvta_generic_to_shared(w2_s);

    // A addresses (bytes)
    const unsigned aInp = inp_sh + ((row0 + aRow) * 88  + aK) * 2;
    const unsigned aH   = h_sh   + ((row0 + aRow) * 264 + aK) * 2;
    // B addresses per 16-col block
    unsigned bW1[2], bW2[2];
#pragma unroll
    for (int j = 0; j < 2; ++j) {
        bW1[j] = w1_sh + ((col0 + j * 16 + bN) * 88  + bK) * 2;
        bW2[j] = w2_sh + ((col0 + j * 16 + bN) * 264 + bK) * 2;
    }

    // --- stage biases + weights into SMEM ---
    if (tid < 768)
        bias_s[tid] = (tid < 256) ? b1g[tid] : (tid < 512 ? b2g[tid - 256] : b3g[tid - 512]);
    {
        const uint4* s1 = (const uint4*)gW1t;
        uint4* d1 = (uint4*)w1_s;
        for (int i = tid; i < 256 * 88 * 2 / 16; i += NTHREADS) d1[i] = s1[i];
        const uint4* s2 = (const uint4*)gW2t;
        uint4* d2 = (uint4*)w2_s;
        for (int i = tid; i < 256 * 264 * 2 / 16; i += NTHREADS) d2[i] = s2[i];
    }

    float agg[4][4];
#pragma unroll
    for (int nt = 0; nt < 4; ++nt) {
        agg[nt][0] = 0.f; agg[nt][1] = 0.f; agg[nt][2] = 0.f; agg[nt][3] = 0.f;
    }
    float acc[4][4];

    __syncthreads();

    // ============================ pair loop ============================
    for (int p = 0; p < 6; ++p) {
        // gather inp tile (64x80): [sel(ag) | body | sel(g) | obj_i | obj_j]
        {
            const int i_ = cPI[p], j_ = cPJ[p];
            const int* sel = cPF[p] ? cFIRST : cSECOND;
            const int oi = 10 + 15 * i_;
            const int oj = 10 + 15 * j_;
            for (int e = tid; e < 64 * 80; e += NTHREADS) {
                int rr = e / 80;
                int c  = e - rr * 80;
                int gr = rowbase + rr;
                float v = 0.f;
                if (gr < B) {
                    if (c < 20)      v = ag[gr * 30 + sel[c]];
                    else if (c < 30) v = obs[gr * 55 + (c - 20)];
                    else if (c < 50) v = g[gr * 30 + sel[c - 30]];
                    else if (c < 65) v = obs[gr * 55 + oi + (c - 50)];
                    else             v = obs[gr * 55 + oj + (c - 65)];
                }
                inp_s[rr * 88 + c] = __float2half_rn(v);
            }
        }
        __syncthreads();  // inp ready; prior GEMM2 reads of h_s done

        // GEMM1: acc = inp @ W1 (K=80)
#pragma unroll
        for (int nt = 0; nt < 4; ++nt) {
            acc[nt][0] = 0.f; acc[nt][1] = 0.f; acc[nt][2] = 0.f; acc[nt][3] = 0.f;
        }
        gemm_tile<5>(aInp, bW1, acc);
        __syncthreads();  // h_s safe to overwrite

        // epilogue1: h = relu(acc + b1) -> fp16 SMEM
#pragma unroll
        for (int nt = 0; nt < 4; ++nt) {
            const int cb = col0 + nt * 8 + q * 2;
            const float bx = bias_s[cb], by = bias_s[cb + 1];
            __half2 v01 = __floats2half2_rn(fmaxf(acc[nt][0] + bx, 0.f),
                                            fmaxf(acc[nt][1] + by, 0.f));
            __half2 v23 = __floats2half2_rn(fmaxf(acc[nt][2] + bx, 0.f),
                                            fmaxf(acc[nt][3] + by, 0.f));
            *(__half2*)&h_s[(row0 + r)     * 264 + cb] = v01;
            *(__half2*)&h_s[(row0 + r + 8) * 264 + cb] = v23;
        }
        __syncthreads();  // h ready

        // GEMM2: acc = h @ W2 (K=256); agg += relu(acc + b2)
#pragma unroll
        for (int nt = 0; nt < 4; ++nt) {
            acc[nt][0] = 0.f; acc[nt][1] = 0.f; acc[nt][2] = 0.f; acc[nt][3] = 0.f;
        }
        gemm_tile<16>(aH, bW2, acc);
#pragma unroll
        for (int nt = 0; nt < 4; ++nt) {
            const int cb = col0 + nt * 8 + q * 2;
            const float bx = bias_s[256 + cb], by = bias_s[256 + cb + 1];
            agg[nt][0] += fmaxf(acc[nt][0] + bx, 0.f);
            agg[nt][1] += fmaxf(acc[nt][1] + by, 0.f);
            agg[nt][2] += fmaxf(acc[nt][2] + bx, 0.f);
            agg[nt][3] += fmaxf(acc[nt][3] + by, 0.f);
        }
    }

    __syncthreads();  // all GEMM2 reads of h_s / w2_s complete

    // stage rho over W2; dump agg (fp16) into h_s as GEMM3 A operand
    {
        const uint4* s2 = (const uint4*)gRHOt;
        uint4* d2 = (uint4*)w2_s;
        for (int i = tid; i < 256 * 264 * 2 / 16; i += NTHREADS) d2[i] = s2[i];
    }
#pragma unroll
    for (int nt = 0; nt < 4; ++nt) {
        const int cb = col0 + nt * 8 + q * 2;
        *(__half2*)&h_s[(row0 + r)     * 264 + cb] = __floats2half2_rn(agg[nt][0], agg[nt][1]);
        *(__half2*)&h_s[(row0 + r + 8) * 264 + cb] = __floats2half2_rn(agg[nt][2], agg[nt][3]);
    }
    __syncthreads();

    // GEMM3: acc = agg @ rho (K=256)
#pragma unroll
    for (int nt = 0; nt < 4; ++nt) {
        acc[nt][0] = 0.f; acc[nt][1] = 0.f; acc[nt][2] = 0.f; acc[nt][3] = 0.f;
    }
    gemm_tile<16>(aH, bW2, acc);
    __syncthreads();  // all reads of h_s done before hr overwrite

    // epilogue3: hr = relu(acc + b3) -> h_s; stage head weights
#pragma unroll
    for (int nt = 0; nt < 4; ++nt) {
        const int cb = col0 + nt * 8 + q * 2;
        const float bx = bias_s[512 + cb], by = bias_s[512 + cb + 1];
        __half2 v01 = __floats2half2_rn(fmaxf(acc[nt][0] + bx, 0.f),
                                        fmaxf(acc[nt][1] + by, 0.f));
        __half2 v23 = __floats2half2_rn(fmaxf(acc[nt][2] + bx, 0.f),
                                        fmaxf(acc[nt][3] + by, 0.f));
        *(__half2*)&h_s[(row0 + r)     * 264 + cb] = v01;
        *(__half2*)&h_s[(row0 + r + 8) * 264 + cb] = v23;
    }
    for (int i = tid; i < 2048; i += NTHREADS)
        hw_s[i] = (i < 1024) ? mean_w[i] : logstd_w[i - 1024];
    __syncthreads();

    // heads: mean / logstd (256 -> 4 each); logstd clipped to [-20, 2]
    if (tid < 512) {
        const int idx = tid;
        const int row = idx >> 3;
        const int o = idx & 7;
        const int head = o >> 2;
        const int j = o & 3;
        const int gr = rowbase + row;
        const __half2* hp = (const __half2*)&h_s[row * 264];
        const float* wp = hw_s + head * 1024 + j;
        float s = 0.f;
#pragma unroll 8
        for (int k2 = 0; k2 < 128; ++k2) {
            float2 hv = __half22float2(hp[k2]);
            s += hv.x * wp[(2 * k2) * 4] + hv.y * wp[(2 * k2 + 1) * 4];
        }
        s += head ? logstd_b[j] : mean_b[j];
        if (head) s = fminf(fmaxf(s, -20.f), 2.f);
        if (gr < B) out[(head ? (size_t)B * 4 : (size_t)0) + (size_t)gr * 4 + j] = s;
    }
}

extern "C" void kernel_launch(void* const* d_in, const int* in_sizes, int n_in,
                              void* d_out, int out_size) {
    const float* obs = (const float*)d_in[0];
    const float* ag  = (const float*)d_in[1];
    const float* g   = (const float*)d_in[2];
    const float* w1  = (const float*)d_in[3];
    const float* b1  = (const float*)d_in[4];
    const float* w2  = (const float*)d_in[5];
    const float* b2  = (const float*)d_in[6];
    const float* rho = (const float*)d_in[7];
    const float* b3  = (const float*)d_in[8];
    const float* mw  = (const float*)d_in[9];
    const float* mb  = (const float*)d_in[10];
    const float* lw  = (const float*)d_in[11];
    const float* lb  = (const float*)d_in[12];
    float* out = (float*)d_out;
    const int B = in_sizes[0] / 55;

    convert_weights_kernel<<<(256 * 256 + 255) / 256, 256>>>(w1, w2, rho);

    cudaFuncSetAttribute(actor_kernel,
                         cudaFuncAttributeMaxDynamicSharedMemorySize, SMEM_BYTES);
    actor_kernel<<<(B + 63) / 64, NTHREADS, SMEM_BYTES>>>(obs, ag, g, b1, b2, b3,
                                                          mw, mb, lw, lb, out, B);
}